// round 12
// baseline (speedup 1.0000x reference)
#include <cuda_runtime.h>

// BackwardConv2D: two transposed 3x3 SAME convs (grad-of-conv) over
// [B=16, n=10] slices of 64x64 images, C_out=64 -> C_in=32, fp32.
//
// out layout (flat): [ w_u (16*131072*10) | b_u (160) | w_l (16*131072*10) | b_l (160) ]

#define PS          388                 // smem pixel stride (64co*6 + 4 pad), mod 32 == 4
#define SMK_FLOATS  18432               // 9 taps * 64 co * 32 ci
#define SMT_FLOATS  (100 * PS)          // 10x10 halo pixels
#define SMR_FLOATS  40                  // 8 warps * 5 n partials
#define SMEM_BYTES  ((SMK_FLOATS + SMT_FLOATS + SMR_FLOATS) * 4)

#define IN_PER_B    2621440             // 262144 * 10
#define OUT_PER_B   1310720             // 131072 * 10
#define OFF_BU      20971520
#define OFF_WL      20971680
#define OFF_BL      41943200

__device__ float g_Kt[SMK_FLOATS];           // K transposed: [tap][co][ci]
__device__ float g_part[2][16 * 2 * 64 * 5]; // bias partials: [branch][(b*2+nh)*64 + tile][n]

__device__ __forceinline__ void fma2(unsigned long long& d, unsigned long long a,
                                     unsigned long long b) {
    asm("fma.rn.f32x2 %0, %1, %2, %0;" : "+l"(d) : "l"(a), "l"(b));
}
__device__ __forceinline__ unsigned long long dup2(float v) {
    unsigned long long r;
    asm("mov.b64 %0, {%1, %1};" : "=l"(r) : "f"(v));
    return r;
}
__device__ __forceinline__ float2 unpack2(unsigned long long v) {
    float2 f;
    asm("mov.b64 {%0, %1}, %2;" : "=f"(f.x), "=f"(f.y) : "l"(v));
    return f;
}

// Transpose kernel [kh][kw][ci][co] -> [tap][co][ci] once per launch.
__global__ void prep_kernel(const float* __restrict__ Kg) {
    int i = blockIdx.x * 256 + threadIdx.x;
    if (i < SMK_FLOATS) {
        int tap = i >> 11;           // /2048
        int r   = i & 2047;
        int co  = r >> 5;
        int ci  = r & 31;
        g_Kt[i] = Kg[tap * 2048 + ci * 64 + co];
    }
}

// One block: (branch implicit via pointers, b, 8x8 tile, n-half of 5).
// 256 threads = 64 core pixels * 4 ci-groups of 8.
__global__ __launch_bounds__(256, 1)
void conv_kernel(const float* __restrict__ in, float* __restrict__ wout,
                 const float* __restrict__ bias, int branch) {
    extern __shared__ float sm[];
    float* smK = sm;                       // weights [tap][co][ci]
    float* smT = sm + SMK_FLOATS;          // tile   [pix][co][n(5, padded row 6)]
    float* smR = smT + SMT_FLOATS;         // warp partials

    const int tid  = threadIdx.x;
    const int tile = blockIdx.x;           // 0..63
    const int ty   = tile >> 3, tx = tile & 7;
    const int b    = blockIdx.y;           // 0..15
    const int nh   = blockIdx.z;           // 0..1
    const int n0   = nh * 5;

    const float* src = in + (size_t)b * IN_PER_B;

    // ---- weights -> smem (coalesced float4 copy) ----
    #pragma unroll 4
    for (int i = tid; i < SMK_FLOATS / 4; i += 256)
        ((float4*)smK)[i] = ((const float4*)g_Kt)[i];

    // ---- halo tile -> smem (zero-padded at image edges) ----
    const int warp = tid >> 5, lane = tid & 31;
    for (int p = warp; p < 100; p += 8) {
        int prow = p / 10;
        int hy = ty * 8 + prow - 1;
        int hx = tx * 8 + (p - prow * 10) - 1;
        bool valid = ((unsigned)hy < 64u) && ((unsigned)hx < 64u);
        const float* g = src + (size_t)(hy * 64 + hx) * 640 + n0;
        float* s = smT + p * PS;
        #pragma unroll
        for (int e = lane; e < 320; e += 32) {
            int co = e / 5;
            int n  = e - co * 5;
            s[co * 6 + n] = valid ? g[co * 10 + n] : 0.0f;
        }
    }
    __syncthreads();

    // ---- compute: each thread: 8 ci (= 4 f32x2 pairs) x 5 n ----
    const int pixc = tid >> 2;             // 0..63
    const int g4   = tid & 3;              // ci group
    const int py   = pixc >> 3, px = pixc & 7;
    const int ci0  = g4 * 8;

    unsigned long long acc[4][5];
    #pragma unroll
    for (int i = 0; i < 4; ++i)
        #pragma unroll
        for (int j = 0; j < 5; ++j) acc[i][j] = 0ull;

    #pragma unroll
    for (int kh = 0; kh < 3; ++kh) {
        #pragma unroll
        for (int kw = 0; kw < 3; ++kw) {
            // y[h,w] gathers z[h+1-kh, w+1-kw]; halo coord = core + (2-kh/kw)
            const float* tp = smT + ((py + 2 - kh) * 10 + (px + 2 - kw)) * PS;
            const float* kp = smK + (kh * 3 + kw) * 2048 + ci0;
            #pragma unroll 4
            for (int co = 0; co < 64; ++co) {
                const float* kq = kp + co * 32;
                ulonglong2 ka = *reinterpret_cast<const ulonglong2*>(kq);
                ulonglong2 kb = *reinterpret_cast<const ulonglong2*>(kq + 4);
                const float* vp = tp + co * 6;
                unsigned long long w0 = dup2(vp[0]);
                unsigned long long w1 = dup2(vp[1]);
                unsigned long long w2 = dup2(vp[2]);
                unsigned long long w3 = dup2(vp[3]);
                unsigned long long w4 = dup2(vp[4]);
                fma2(acc[0][0], ka.x, w0); fma2(acc[1][0], ka.y, w0);
                fma2(acc[2][0], kb.x, w0); fma2(acc[3][0], kb.y, w0);
                fma2(acc[0][1], ka.x, w1); fma2(acc[1][1], ka.y, w1);
                fma2(acc[2][1], kb.x, w1); fma2(acc[3][1], kb.y, w1);
                fma2(acc[0][2], ka.x, w2); fma2(acc[1][2], ka.y, w2);
                fma2(acc[2][2], kb.x, w2); fma2(acc[3][2], kb.y, w2);
                fma2(acc[0][3], ka.x, w3); fma2(acc[1][3], ka.y, w3);
                fma2(acc[2][3], kb.x, w3); fma2(acc[3][3], kb.y, w3);
                fma2(acc[0][4], ka.x, w4); fma2(acc[1][4], ka.y, w4);
                fma2(acc[2][4], kb.x, w4); fma2(acc[3][4], kb.y, w4);
            }
        }
    }

    // ---- write outputs: out[((h*64+w)*32+ci)*10 + n] ----
    {
        const int hw = (ty * 8 + py) * 64 + (tx * 8 + px);
        float* op = wout + (size_t)b * OUT_PER_B + (size_t)(hw * 32 + ci0) * 10 + n0;
        #pragma unroll
        for (int c2 = 0; c2 < 4; ++c2) {
            #pragma unroll
            for (int n = 0; n < 5; ++n) {
                float2 f = unpack2(acc[c2][n]);
                op[(2 * c2) * 10 + n]     = f.x;
                op[(2 * c2 + 1) * 10 + n] = f.y;
            }
        }
    }

    // ---- bias partial: sum over core pixel, this thread's 16 co, 5 n ----
    float bn[5] = {0.f, 0.f, 0.f, 0.f, 0.f};
    {
        const float* cp2 = smT + ((py + 1) * 10 + (px + 1)) * PS + g4 * 16 * 6;
        #pragma unroll 4
        for (int co = 0; co < 16; ++co) {
            float bw = __ldg(bias + g4 * 16 + co);
            const float* v = cp2 + co * 6;
            bn[0] += v[0] * bw; bn[1] += v[1] * bw; bn[2] += v[2] * bw;
            bn[3] += v[3] * bw; bn[4] += v[4] * bw;
        }
    }
    #pragma unroll
    for (int off = 16; off; off >>= 1)
        #pragma unroll
        for (int n = 0; n < 5; ++n)
            bn[n] += __shfl_down_sync(0xffffffffu, bn[n], off);
    if (lane == 0) {
        #pragma unroll
        for (int n = 0; n < 5; ++n) smR[warp * 5 + n] = bn[n];
    }
    __syncthreads();
    if (tid < 5) {
        float s = 0.f;
        #pragma unroll
        for (int w2 = 0; w2 < 8; ++w2) s += smR[w2 * 5 + tid];
        g_part[branch][((b * 2 + nh) * 64 + tile) * 5 + tid] = s;
    }
}

// Deterministic bias reduction: b_new[b,n] = b_out[b,n] + sum over 64 tile partials.
__global__ void bias_reduce(const float* __restrict__ bu, const float* __restrict__ bl,
                            float* __restrict__ out) {
    int i = blockIdx.x * 64 + threadIdx.x;
    if (i >= 320) return;
    int branch = i / 160;
    int r = i - branch * 160;       // b*10 + n
    int b = r / 10;
    int n = r - b * 10;
    int nhh = n / 5;
    int nl = n - nhh * 5;
    float s = branch ? bl[r] : bu[r];
    const float* p = &g_part[branch][((b * 2 + nhh) * 64) * 5 + nl];
    #pragma unroll 8
    for (int t = 0; t < 64; ++t) s += p[t * 5];
    out[(branch ? OFF_BL : OFF_BU) + r] = s;
}

extern "C" void kernel_launch(void* const* d_in, const int* in_sizes, int n_in,
                              void* d_out, int out_size) {
    const float* wu   = (const float*)d_in[0];
    const float* bu   = (const float*)d_in[1];
    const float* wl   = (const float*)d_in[2];
    const float* bl   = (const float*)d_in[3];
    const float* Kg   = (const float*)d_in[4];
    const float* bias = (const float*)d_in[5];
    float* out = (float*)d_out;

    cudaFuncSetAttribute(conv_kernel, cudaFuncAttributeMaxDynamicSharedMemorySize, SMEM_BYTES);

    prep_kernel<<<(SMK_FLOATS + 255) / 256, 256>>>(Kg);

    dim3 grid(64, 16, 2);
    conv_kernel<<<grid, 256, SMEM_BYTES>>>(wu, out, bias, 0);
    conv_kernel<<<grid, 256, SMEM_BYTES>>>(wl, out + OFF_WL, bias, 1);

    bias_reduce<<<5, 64>>>(bu, bl, out);
}

// round 13
// speedup vs baseline: 1.0094x; 1.0094x over previous
#include <cuda_runtime.h>

// BackwardConv2D: two transposed 3x3 SAME convs (grad-of-conv) over
// [B=16, n=10] slices of 64x64 images, C_out=64 -> C_in=32, fp32.
//
// out layout (flat): [ w_u (16*131072*10) | b_u (160) | w_l (16*131072*10) | b_l (160) ]

#define PS          388                 // smem pixel stride (64co*6 + 4 pad), mod 32 == 4
#define SMK_FLOATS  18432               // 9 taps * 64 co * 32 ci
#define SMT_FLOATS  (100 * PS)          // 10x10 halo pixels
#define SMR_FLOATS  40                  // 8 warps * 5 n partials
#define SMEM_BYTES  ((SMK_FLOATS + SMT_FLOATS + SMR_FLOATS) * 4)

#define IN_PER_B    2621440             // 262144 * 10
#define OUT_PER_B   1310720             // 131072 * 10
#define OFF_BU      20971520
#define OFF_WL      20971680
#define OFF_BL      41943200

__device__ float g_Kt[SMK_FLOATS];           // K transposed: [tap][co][ci]
__device__ float g_part[2][16 * 2 * 64 * 5]; // bias partials: [branch][(b*2+nh)*64 + tile][n]

__device__ __forceinline__ void fma2(unsigned long long& d, unsigned long long a,
                                     unsigned long long b) {
    asm("fma.rn.f32x2 %0, %1, %2, %0;" : "+l"(d) : "l"(a), "l"(b));
}
__device__ __forceinline__ unsigned long long dup2(float v) {
    unsigned long long r;
    asm("mov.b64 %0, {%1, %1};" : "=l"(r) : "f"(v));
    return r;
}
__device__ __forceinline__ float2 unpack2(unsigned long long v) {
    float2 f;
    asm("mov.b64 {%0, %1}, %2;" : "=f"(f.x), "=f"(f.y) : "l"(v));
    return f;
}

// Transpose kernel [kh][kw][ci][co] -> [tap][co][ci] once per launch.
__global__ void prep_kernel(const float* __restrict__ Kg) {
    int i = blockIdx.x * 256 + threadIdx.x;
    if (i < SMK_FLOATS) {
        int tap = i >> 11;           // /2048
        int r   = i & 2047;
        int co  = r >> 5;
        int ci  = r & 31;
        g_Kt[i] = Kg[tap * 2048 + ci * 64 + co];
    }
}

// One block: (branch implicit via pointers, b, 8x8 tile, n-half of 5).
// 256 threads = 64 core pixels * 4 ci-groups of 8.
__global__ __launch_bounds__(256, 1)
void conv_kernel(const float* __restrict__ in, float* __restrict__ wout,
                 const float* __restrict__ bias, int branch) {
    extern __shared__ float sm[];
    float* smK = sm;                       // weights [tap][co][ci]
    float* smT = sm + SMK_FLOATS;          // tile   [pix][co][n(5, padded row 6)]
    float* smR = smT + SMT_FLOATS;         // warp partials

    const int tid  = threadIdx.x;
    const int tile = blockIdx.x;           // 0..63
    const int ty   = tile >> 3, tx = tile & 7;
    const int b    = blockIdx.y;           // 0..15
    const int nh   = blockIdx.z;           // 0..1
    const int n0   = nh * 5;

    const float* src = in + (size_t)b * IN_PER_B;

    // ---- weights -> smem (coalesced float4 copy) ----
    #pragma unroll 4
    for (int i = tid; i < SMK_FLOATS / 4; i += 256)
        ((float4*)smK)[i] = ((const float4*)g_Kt)[i];

    // ---- halo tile -> smem (zero-padded at image edges) ----
    const int warp = tid >> 5, lane = tid & 31;
    for (int p = warp; p < 100; p += 8) {
        int prow = p / 10;
        int hy = ty * 8 + prow - 1;
        int hx = tx * 8 + (p - prow * 10) - 1;
        bool valid = ((unsigned)hy < 64u) && ((unsigned)hx < 64u);
        const float* g = src + (size_t)(hy * 64 + hx) * 640 + n0;
        float* s = smT + p * PS;
        #pragma unroll
        for (int e = lane; e < 320; e += 32) {
            int co = e / 5;
            int n  = e - co * 5;
            s[co * 6 + n] = valid ? g[co * 10 + n] : 0.0f;
        }
    }
    __syncthreads();

    // ---- compute: each thread: 8 ci (= 4 f32x2 pairs) x 5 n ----
    const int pixc = tid >> 2;             // 0..63
    const int g4   = tid & 3;              // ci group
    const int py   = pixc >> 3, px = pixc & 7;
    const int ci0  = g4 * 8;

    unsigned long long acc[4][5];
    #pragma unroll
    for (int i = 0; i < 4; ++i)
        #pragma unroll
        for (int j = 0; j < 5; ++j) acc[i][j] = 0ull;

    #pragma unroll
    for (int kh = 0; kh < 3; ++kh) {
        #pragma unroll
        for (int kw = 0; kw < 3; ++kw) {
            // y[h,w] gathers z[h+1-kh, w+1-kw]; halo coord = core + (2-kh/kw)
            const float* tp = smT + ((py + 2 - kh) * 10 + (px + 2 - kw)) * PS;
            const float* kp = smK + (kh * 3 + kw) * 2048 + ci0;
            #pragma unroll 4
            for (int co = 0; co < 64; ++co) {
                const float* kq = kp + co * 32;
                ulonglong2 ka = *reinterpret_cast<const ulonglong2*>(kq);
                ulonglong2 kb = *reinterpret_cast<const ulonglong2*>(kq + 4);
                const float* vp = tp + co * 6;
                unsigned long long w0 = dup2(vp[0]);
                unsigned long long w1 = dup2(vp[1]);
                unsigned long long w2 = dup2(vp[2]);
                unsigned long long w3 = dup2(vp[3]);
                unsigned long long w4 = dup2(vp[4]);
                fma2(acc[0][0], ka.x, w0); fma2(acc[1][0], ka.y, w0);
                fma2(acc[2][0], kb.x, w0); fma2(acc[3][0], kb.y, w0);
                fma2(acc[0][1], ka.x, w1); fma2(acc[1][1], ka.y, w1);
                fma2(acc[2][1], kb.x, w1); fma2(acc[3][1], kb.y, w1);
                fma2(acc[0][2], ka.x, w2); fma2(acc[1][2], ka.y, w2);
                fma2(acc[2][2], kb.x, w2); fma2(acc[3][2], kb.y, w2);
                fma2(acc[0][3], ka.x, w3); fma2(acc[1][3], ka.y, w3);
                fma2(acc[2][3], kb.x, w3); fma2(acc[3][3], kb.y, w3);
                fma2(acc[0][4], ka.x, w4); fma2(acc[1][4], ka.y, w4);
                fma2(acc[2][4], kb.x, w4); fma2(acc[3][4], kb.y, w4);
            }
        }
    }

    // ---- write outputs: out[((h*64+w)*32+ci)*10 + n] ----
    {
        const int hw = (ty * 8 + py) * 64 + (tx * 8 + px);
        float* op = wout + (size_t)b * OUT_PER_B + (size_t)(hw * 32 + ci0) * 10 + n0;
        #pragma unroll
        for (int c2 = 0; c2 < 4; ++c2) {
            #pragma unroll
            for (int n = 0; n < 5; ++n) {
                float2 f = unpack2(acc[c2][n]);
                op[(2 * c2) * 10 + n]     = f.x;
                op[(2 * c2 + 1) * 10 + n] = f.y;
            }
        }
    }

    // ---- bias partial: sum over core pixel, this thread's 16 co, 5 n ----
    float bn[5] = {0.f, 0.f, 0.f, 0.f, 0.f};
    {
        const float* cp2 = smT + ((py + 1) * 10 + (px + 1)) * PS + g4 * 16 * 6;
        #pragma unroll 4
        for (int co = 0; co < 16; ++co) {
            float bw = __ldg(bias + g4 * 16 + co);
            const float* v = cp2 + co * 6;
            bn[0] += v[0] * bw; bn[1] += v[1] * bw; bn[2] += v[2] * bw;
            bn[3] += v[3] * bw; bn[4] += v[4] * bw;
        }
    }
    #pragma unroll
    for (int off = 16; off; off >>= 1)
        #pragma unroll
        for (int n = 0; n < 5; ++n)
            bn[n] += __shfl_down_sync(0xffffffffu, bn[n], off);
    if (lane == 0) {
        #pragma unroll
        for (int n = 0; n < 5; ++n) smR[warp * 5 + n] = bn[n];
    }
    __syncthreads();
    if (tid < 5) {
        float s = 0.f;
        #pragma unroll
        for (int w2 = 0; w2 < 8; ++w2) s += smR[w2 * 5 + tid];
        g_part[branch][((b * 2 + nh) * 64 + tile) * 5 + tid] = s;
    }
}

// Deterministic bias reduction: b_new[b,n] = b_out[b,n] + sum over 64 tile partials.
__global__ void bias_reduce(const float* __restrict__ bu, const float* __restrict__ bl,
                            float* __restrict__ out) {
    int i = blockIdx.x * 64 + threadIdx.x;
    if (i >= 320) return;
    int branch = i / 160;
    int r = i - branch * 160;       // b*10 + n
    int b = r / 10;
    int n = r - b * 10;
    int nhh = n / 5;
    int nl = n - nhh * 5;
    float s = branch ? bl[r] : bu[r];
    const float* p = &g_part[branch][((b * 2 + nhh) * 64) * 5 + nl];
    #pragma unroll 8
    for (int t = 0; t < 64; ++t) s += p[t * 5];
    out[(branch ? OFF_BL : OFF_BU) + r] = s;
}

extern "C" void kernel_launch(void* const* d_in, const int* in_sizes, int n_in,
                              void* d_out, int out_size) {
    const float* wu   = (const float*)d_in[0];
    const float* bu   = (const float*)d_in[1];
    const float* wl   = (const float*)d_in[2];
    const float* bl   = (const float*)d_in[3];
    const float* Kg   = (const float*)d_in[4];
    const float* bias = (const float*)d_in[5];
    float* out = (float*)d_out;

    cudaFuncSetAttribute(conv_kernel, cudaFuncAttributeMaxDynamicSharedMemorySize, SMEM_BYTES);

    prep_kernel<<<(SMK_FLOATS + 255) / 256, 256>>>(Kg);

    dim3 grid(64, 16, 2);
    conv_kernel<<<grid, 256, SMEM_BYTES>>>(wu, out, bias, 0);
    conv_kernel<<<grid, 256, SMEM_BYTES>>>(wl, out + OFF_WL, bias, 1);

    bias_reduce<<<5, 64>>>(bu, bl, out);
}

// round 14
// speedup vs baseline: 1.0112x; 1.0018x over previous
#include <cuda_runtime.h>

// BackwardConv2D: two transposed 3x3 SAME convs (grad-of-conv) over
// [B=16, n=10] slices of 64x64 images, C_out=64 -> C_in=32, fp32.
//
// out layout (flat): [ w_u (16*131072*10) | b_u (160) | w_l (16*131072*10) | b_l (160) ]

#define PS          388                 // smem pixel stride (64co*6 + 4 pad), mod 32 == 4
#define SMK_FLOATS  18432               // 9 taps * 64 co * 32 ci
#define SMT_FLOATS  (100 * PS)          // 10x10 halo pixels
#define SMR_FLOATS  40                  // 8 warps * 5 n partials
#define SMEM_BYTES  ((SMK_FLOATS + SMT_FLOATS + SMR_FLOATS) * 4)

#define IN_PER_B    2621440             // 262144 * 10
#define OUT_PER_B   1310720             // 131072 * 10
#define OFF_BU      20971520
#define OFF_WL      20971680
#define OFF_BL      41943200

__device__ float g_Kt[SMK_FLOATS];           // K transposed: [tap][co][ci]
__device__ float g_part[2][16 * 2 * 64 * 5]; // bias partials: [branch][(b*2+nh)*64 + tile][n]

__device__ __forceinline__ void fma2(unsigned long long& d, unsigned long long a,
                                     unsigned long long b) {
    asm("fma.rn.f32x2 %0, %1, %2, %0;" : "+l"(d) : "l"(a), "l"(b));
}
__device__ __forceinline__ unsigned long long dup2(float v) {
    unsigned long long r;
    asm("mov.b64 %0, {%1, %1};" : "=l"(r) : "f"(v));
    return r;
}
__device__ __forceinline__ float2 unpack2(unsigned long long v) {
    float2 f;
    asm("mov.b64 {%0, %1}, %2;" : "=f"(f.x), "=f"(f.y) : "l"(v));
    return f;
}

// Transpose kernel [kh][kw][ci][co] -> [tap][co][ci] once per launch.
__global__ void prep_kernel(const float* __restrict__ Kg) {
    int i = blockIdx.x * 256 + threadIdx.x;
    if (i < SMK_FLOATS) {
        int tap = i >> 11;           // /2048
        int r   = i & 2047;
        int co  = r >> 5;
        int ci  = r & 31;
        g_Kt[i] = Kg[tap * 2048 + ci * 64 + co];
    }
}

// One block: (branch implicit via pointers, b, 8x8 tile, n-half of 5).
// 256 threads = 64 core pixels * 4 ci-groups of 8.
__global__ __launch_bounds__(256, 1)
void conv_kernel(const float* __restrict__ in, float* __restrict__ wout,
                 const float* __restrict__ bias, int branch) {
    extern __shared__ float sm[];
    float* smK = sm;                       // weights [tap][co][ci]
    float* smT = sm + SMK_FLOATS;          // tile   [pix][co][n(5, padded row 6)]
    float* smR = smT + SMT_FLOATS;         // warp partials

    const int tid  = threadIdx.x;
    const int tile = blockIdx.x;           // 0..63
    const int ty   = tile >> 3, tx = tile & 7;
    const int b    = blockIdx.y;           // 0..15
    const int nh   = blockIdx.z;           // 0..1
    const int n0   = nh * 5;

    const float* src = in + (size_t)b * IN_PER_B;

    // ---- weights -> smem (coalesced float4 copy) ----
    #pragma unroll 4
    for (int i = tid; i < SMK_FLOATS / 4; i += 256)
        ((float4*)smK)[i] = ((const float4*)g_Kt)[i];

    // ---- halo tile -> smem (zero-padded at image edges) ----
    const int warp = tid >> 5, lane = tid & 31;
    for (int p = warp; p < 100; p += 8) {
        int prow = p / 10;
        int hy = ty * 8 + prow - 1;
        int hx = tx * 8 + (p - prow * 10) - 1;
        bool valid = ((unsigned)hy < 64u) && ((unsigned)hx < 64u);
        const float* g = src + (size_t)(hy * 64 + hx) * 640 + n0;
        float* s = smT + p * PS;
        #pragma unroll
        for (int e = lane; e < 320; e += 32) {
            int co = e / 5;
            int n  = e - co * 5;
            s[co * 6 + n] = valid ? g[co * 10 + n] : 0.0f;
        }
    }
    __syncthreads();

    // ---- compute: each thread: 8 ci (= 4 f32x2 pairs) x 5 n ----
    const int pixc = tid >> 2;             // 0..63
    const int g4   = tid & 3;              // ci group
    const int py   = pixc >> 3, px = pixc & 7;
    const int ci0  = g4 * 8;

    unsigned long long acc[4][5];
    #pragma unroll
    for (int i = 0; i < 4; ++i)
        #pragma unroll
        for (int j = 0; j < 5; ++j) acc[i][j] = 0ull;

    #pragma unroll
    for (int kh = 0; kh < 3; ++kh) {
        #pragma unroll
        for (int kw = 0; kw < 3; ++kw) {
            // y[h,w] gathers z[h+1-kh, w+1-kw]; halo coord = core + (2-kh/kw)
            const float* tp = smT + ((py + 2 - kh) * 10 + (px + 2 - kw)) * PS;
            const float* kp = smK + (kh * 3 + kw) * 2048 + ci0;
            #pragma unroll 4
            for (int co = 0; co < 64; ++co) {
                const float* kq = kp + co * 32;
                ulonglong2 ka = *reinterpret_cast<const ulonglong2*>(kq);
                ulonglong2 kb = *reinterpret_cast<const ulonglong2*>(kq + 4);
                const float* vp = tp + co * 6;
                unsigned long long w0 = dup2(vp[0]);
                unsigned long long w1 = dup2(vp[1]);
                unsigned long long w2 = dup2(vp[2]);
                unsigned long long w3 = dup2(vp[3]);
                unsigned long long w4 = dup2(vp[4]);
                fma2(acc[0][0], ka.x, w0); fma2(acc[1][0], ka.y, w0);
                fma2(acc[2][0], kb.x, w0); fma2(acc[3][0], kb.y, w0);
                fma2(acc[0][1], ka.x, w1); fma2(acc[1][1], ka.y, w1);
                fma2(acc[2][1], kb.x, w1); fma2(acc[3][1], kb.y, w1);
                fma2(acc[0][2], ka.x, w2); fma2(acc[1][2], ka.y, w2);
                fma2(acc[2][2], kb.x, w2); fma2(acc[3][2], kb.y, w2);
                fma2(acc[0][3], ka.x, w3); fma2(acc[1][3], ka.y, w3);
                fma2(acc[2][3], kb.x, w3); fma2(acc[3][3], kb.y, w3);
                fma2(acc[0][4], ka.x, w4); fma2(acc[1][4], ka.y, w4);
                fma2(acc[2][4], kb.x, w4); fma2(acc[3][4], kb.y, w4);
            }
        }
    }

    // ---- write outputs: out[((h*64+w)*32+ci)*10 + n] ----
    {
        const int hw = (ty * 8 + py) * 64 + (tx * 8 + px);
        float* op = wout + (size_t)b * OUT_PER_B + (size_t)(hw * 32 + ci0) * 10 + n0;
        #pragma unroll
        for (int c2 = 0; c2 < 4; ++c2) {
            #pragma unroll
            for (int n = 0; n < 5; ++n) {
                float2 f = unpack2(acc[c2][n]);
                op[(2 * c2) * 10 + n]     = f.x;
                op[(2 * c2 + 1) * 10 + n] = f.y;
            }
        }
    }

    // ---- bias partial: sum over core pixel, this thread's 16 co, 5 n ----
    float bn[5] = {0.f, 0.f, 0.f, 0.f, 0.f};
    {
        const float* cp2 = smT + ((py + 1) * 10 + (px + 1)) * PS + g4 * 16 * 6;
        #pragma unroll 4
        for (int co = 0; co < 16; ++co) {
            float bw = __ldg(bias + g4 * 16 + co);
            const float* v = cp2 + co * 6;
            bn[0] += v[0] * bw; bn[1] += v[1] * bw; bn[2] += v[2] * bw;
            bn[3] += v[3] * bw; bn[4] += v[4] * bw;
        }
    }
    #pragma unroll
    for (int off = 16; off; off >>= 1)
        #pragma unroll
        for (int n = 0; n < 5; ++n)
            bn[n] += __shfl_down_sync(0xffffffffu, bn[n], off);
    if (lane == 0) {
        #pragma unroll
        for (int n = 0; n < 5; ++n) smR[warp * 5 + n] = bn[n];
    }
    __syncthreads();
    if (tid < 5) {
        float s = 0.f;
        #pragma unroll
        for (int w2 = 0; w2 < 8; ++w2) s += smR[w2 * 5 + tid];
        g_part[branch][((b * 2 + nh) * 64 + tile) * 5 + tid] = s;
    }
}

// Deterministic bias reduction: b_new[b,n] = b_out[b,n] + sum over 64 tile partials.
__global__ void bias_reduce(const float* __restrict__ bu, const float* __restrict__ bl,
                            float* __restrict__ out) {
    int i = blockIdx.x * 64 + threadIdx.x;
    if (i >= 320) return;
    int branch = i / 160;
    int r = i - branch * 160;       // b*10 + n
    int b = r / 10;
    int n = r - b * 10;
    int nhh = n / 5;
    int nl = n - nhh * 5;
    float s = branch ? bl[r] : bu[r];
    const float* p = &g_part[branch][((b * 2 + nhh) * 64) * 5 + nl];
    #pragma unroll 8
    for (int t = 0; t < 64; ++t) s += p[t * 5];
    out[(branch ? OFF_BL : OFF_BU) + r] = s;
}

extern "C" void kernel_launch(void* const* d_in, const int* in_sizes, int n_in,
                              void* d_out, int out_size) {
    const float* wu   = (const float*)d_in[0];
    const float* bu   = (const float*)d_in[1];
    const float* wl   = (const float*)d_in[2];
    const float* bl   = (const float*)d_in[3];
    const float* Kg   = (const float*)d_in[4];
    const float* bias = (const float*)d_in[5];
    float* out = (float*)d_out;

    cudaFuncSetAttribute(conv_kernel, cudaFuncAttributeMaxDynamicSharedMemorySize, SMEM_BYTES);

    prep_kernel<<<(SMK_FLOATS + 255) / 256, 256>>>(Kg);

    dim3 grid(64, 16, 2);
    conv_kernel<<<grid, 256, SMEM_BYTES>>>(wu, out, bias, 0);
    conv_kernel<<<grid, 256, SMEM_BYTES>>>(wl, out + OFF_WL, bias, 1);

    bias_reduce<<<5, 64>>>(bu, bl, out);
}

// round 15
// speedup vs baseline: 1.1166x; 1.1041x over previous
#include <cuda_runtime.h>

// BackwardConv2D: two transposed 3x3 SAME convs (grad-of-conv) over
// [B=16, n=10] slices of 64x64 images, C_out=64 -> C_in=32, fp32.
//
// out layout (flat): [ w_u (16*131072*10) | b_u (160) | w_l (16*131072*10) | b_l (160) ]
//
// R14 -> R15: co split into 2 passes of 32 channels -> smem 229KB -> 102.6KB,
// 2 CTAs/SM (4 warps/SMSP) to hide LDS latency. Both branches in one launch.

#define PS          164                 // smem pixel stride: 32co*5n + 4 pad (mod 32 == 4)
#define SMK_FLOATS  9216                // 9 taps * 32 co * 32 ci  (one co-half)
#define SMT_FLOATS  (100 * PS)          // 10x10 halo pixels
#define SMR_FLOATS  40                  // 8 warps * 5 n partials
#define SMEM_BYTES  ((SMK_FLOATS + SMT_FLOATS + SMR_FLOATS) * 4)

#define IN_PER_B    2621440             // 262144 * 10
#define OUT_PER_B   1310720             // 131072 * 10
#define OFF_BU      20971520
#define OFF_WL      20971680
#define OFF_BL      41943200

__device__ float g_Kt[18432];                // K transposed: [tap][co(64)][ci(32)]
__device__ float g_part[2][16 * 2 * 64 * 5]; // bias partials: [branch][(b*2+nh)*64 + tile][n]

__device__ __forceinline__ void fma2(unsigned long long& d, unsigned long long a,
                                     unsigned long long b) {
    asm("fma.rn.f32x2 %0, %1, %2, %0;" : "+l"(d) : "l"(a), "l"(b));
}
__device__ __forceinline__ unsigned long long dup2(float v) {
    unsigned long long r;
    asm("mov.b64 %0, {%1, %1};" : "=l"(r) : "f"(v));
    return r;
}
__device__ __forceinline__ float2 unpack2(unsigned long long v) {
    float2 f;
    asm("mov.b64 {%0, %1}, %2;" : "=f"(f.x), "=f"(f.y) : "l"(v));
    return f;
}

// Transpose kernel [kh][kw][ci][co] -> [tap][co][ci] once per launch.
__global__ void prep_kernel(const float* __restrict__ Kg) {
    int i = blockIdx.x * 256 + threadIdx.x;
    if (i < 18432) {
        int tap = i >> 11;           // /2048
        int r   = i & 2047;
        int co  = r >> 5;
        int ci  = r & 31;
        g_Kt[i] = Kg[tap * 2048 + ci * 64 + co];
    }
}

// One block: (branch, b, 8x8 tile, n-half of 5); 2 co-passes of 32 channels.
// 256 threads = 64 core pixels * 4 ci-groups of 8.
__global__ __launch_bounds__(256, 2)
void conv_kernel(const float* __restrict__ wu, const float* __restrict__ wl,
                 float* __restrict__ out, const float* __restrict__ bias) {
    extern __shared__ float sm[];
    float* smK = sm;                       // weights half [tap][co(32)][ci(32)]
    float* smT = sm + SMK_FLOATS;          // tile [pix][co(32)][n(5)] stride PS
    float* smR = smT + SMT_FLOATS;         // warp partials

    const int tid    = threadIdx.x;
    const int tile   = blockIdx.x;         // 0..63
    const int ty     = tile >> 3, tx = tile & 7;
    const int b      = blockIdx.y;         // 0..15
    const int z      = blockIdx.z;         // 0..3
    const int branch = z >> 1;
    const int nh     = z & 1;
    const int n0     = nh * 5;

    const float* src = (branch ? wl : wu) + (size_t)b * IN_PER_B;
    float* wout      = out + (branch ? OFF_WL : 0);

    const int warp = tid >> 5, lane = tid & 31;
    const int pixc = tid >> 2;             // 0..63
    const int g4   = tid & 3;              // ci group
    const int py   = pixc >> 3, px = pixc & 7;
    const int ci0  = g4 * 8;

    unsigned long long acc[4][5];
    #pragma unroll
    for (int i = 0; i < 4; ++i)
        #pragma unroll
        for (int j = 0; j < 5; ++j) acc[i][j] = 0ull;

    float bn[5] = {0.f, 0.f, 0.f, 0.f, 0.f};

    for (int coh = 0; coh < 2; ++coh) {
        if (coh) __syncthreads();          // everyone done reading previous tile

        // ---- weights half -> smem (coalesced float4 copy) ----
        // g_Kt[tap][co][ci]: half = per-tap chunk of 1024 floats at offset coh*1024
        #pragma unroll
        for (int i = tid; i < SMK_FLOATS / 4; i += 256) {
            int tap = i >> 8;              // /256 float4 per tap-half
            int w4  = i & 255;
            ((float4*)smK)[i] = ((const float4*)g_Kt)[tap * 512 + coh * 256 + w4];
        }

        // ---- halo tile half -> smem (zero-padded at image edges) ----
        for (int p = warp; p < 100; p += 8) {
            int prow = p / 10;
            int hy = ty * 8 + prow - 1;
            int hx = tx * 8 + (p - prow * 10) - 1;
            bool valid = ((unsigned)hy < 64u) && ((unsigned)hx < 64u);
            const float* g = src + (size_t)(hy * 64 + hx) * 640 + coh * 320 + n0;
            float* s = smT + p * PS;
            #pragma unroll
            for (int e = lane; e < 160; e += 32) {
                int co = e / 5;
                int n  = e - co * 5;
                s[e] = valid ? g[co * 10 + n] : 0.0f;   // layout stride co*5+n == e
            }
        }
        __syncthreads();

        // ---- compute: each thread: 8 ci (= 4 f32x2 pairs) x 5 n, 32 co ----
        #pragma unroll
        for (int kh = 0; kh < 3; ++kh) {
            #pragma unroll
            for (int kw = 0; kw < 3; ++kw) {
                // y[h,w] gathers z[h+1-kh, w+1-kw]; halo coord = core + (2-kh/kw)
                const float* tp = smT + ((py + 2 - kh) * 10 + (px + 2 - kw)) * PS;
                const float* kp = smK + (kh * 3 + kw) * 1024 + ci0;
                #pragma unroll 2
                for (int co = 0; co < 32; ++co) {
                    const float* kq = kp + co * 32;
                    ulonglong2 ka = *reinterpret_cast<const ulonglong2*>(kq);
                    ulonglong2 kb = *reinterpret_cast<const ulonglong2*>(kq + 4);
                    const float* vp = tp + co * 5;
                    unsigned long long w0 = dup2(vp[0]);
                    unsigned long long w1 = dup2(vp[1]);
                    unsigned long long w2 = dup2(vp[2]);
                    unsigned long long w3 = dup2(vp[3]);
                    unsigned long long w4 = dup2(vp[4]);
                    fma2(acc[0][0], ka.x, w0); fma2(acc[1][0], ka.y, w0);
                    fma2(acc[2][0], kb.x, w0); fma2(acc[3][0], kb.y, w0);
                    fma2(acc[0][1], ka.x, w1); fma2(acc[1][1], ka.y, w1);
                    fma2(acc[2][1], kb.x, w1); fma2(acc[3][1], kb.y, w1);
                    fma2(acc[0][2], ka.x, w2); fma2(acc[1][2], ka.y, w2);
                    fma2(acc[2][2], kb.x, w2); fma2(acc[3][2], kb.y, w2);
                    fma2(acc[0][3], ka.x, w3); fma2(acc[1][3], ka.y, w3);
                    fma2(acc[2][3], kb.x, w3); fma2(acc[3][3], kb.y, w3);
                    fma2(acc[0][4], ka.x, w4); fma2(acc[1][4], ka.y, w4);
                    fma2(acc[2][4], kb.x, w4); fma2(acc[3][4], kb.y, w4);
                }
            }
        }

        // ---- bias partial: core pixel, this thread's 8 co of this half, 5 n ----
        {
            const float* cp2 = smT + ((py + 1) * 10 + (px + 1)) * PS + g4 * 40;
            const float* bp  = bias + coh * 32 + g4 * 8;
            #pragma unroll
            for (int co = 0; co < 8; ++co) {
                float bw = __ldg(bp + co);
                const float* v = cp2 + co * 5;
                bn[0] += v[0] * bw; bn[1] += v[1] * bw; bn[2] += v[2] * bw;
                bn[3] += v[3] * bw; bn[4] += v[4] * bw;
            }
        }
    }

    // ---- write outputs: out[((h*64+w)*32+ci)*10 + n] ----
    {
        const int hw = (ty * 8 + py) * 64 + (tx * 8 + px);
        float* op = wout + (size_t)b * OUT_PER_B + (size_t)(hw * 32 + ci0) * 10 + n0;
        #pragma unroll
        for (int c2 = 0; c2 < 4; ++c2) {
            #pragma unroll
            for (int n = 0; n < 5; ++n) {
                float2 f = unpack2(acc[c2][n]);
                op[(2 * c2) * 10 + n]     = f.x;
                op[(2 * c2 + 1) * 10 + n] = f.y;
            }
        }
    }

    // ---- bias reduce across warp (8 px * 4 g4-groups) ----
    #pragma unroll
    for (int off = 16; off; off >>= 1)
        #pragma unroll
        for (int n = 0; n < 5; ++n)
            bn[n] += __shfl_down_sync(0xffffffffu, bn[n], off);
    if (lane == 0) {
        #pragma unroll
        for (int n = 0; n < 5; ++n) smR[warp * 5 + n] = bn[n];
    }
    __syncthreads();
    if (tid < 5) {
        float s = 0.f;
        #pragma unroll
        for (int w2 = 0; w2 < 8; ++w2) s += smR[w2 * 5 + tid];
        g_part[branch][((b * 2 + nh) * 64 + tile) * 5 + tid] = s;
    }
}

// Deterministic bias reduction: b_new[b,n] = b_out[b,n] + sum over 64 tile partials.
__global__ void bias_reduce(const float* __restrict__ bu, const float* __restrict__ bl,
                            float* __restrict__ out) {
    int i = blockIdx.x * 64 + threadIdx.x;
    if (i >= 320) return;
    int branch = i / 160;
    int r = i - branch * 160;       // b*10 + n
    int b = r / 10;
    int n = r - b * 10;
    int nhh = n / 5;
    int nl = n - nhh * 5;
    float s = branch ? bl[r] : bu[r];
    const float* p = &g_part[branch][((b * 2 + nhh) * 64) * 5 + nl];
    #pragma unroll 8
    for (int t = 0; t < 64; ++t) s += p[t * 5];
    out[(branch ? OFF_BL : OFF_BU) + r] = s;
}

extern "C" void kernel_launch(void* const* d_in, const int* in_sizes, int n_in,
                              void* d_out, int out_size) {
    const float* wu   = (const float*)d_in[0];
    const float* bu   = (const float*)d_in[1];
    const float* wl   = (const float*)d_in[2];
    const float* bl   = (const float*)d_in[3];
    const float* Kg   = (const float*)d_in[4];
    const float* bias = (const float*)d_in[5];
    float* out = (float*)d_out;

    cudaFuncSetAttribute(conv_kernel, cudaFuncAttributeMaxDynamicSharedMemorySize, SMEM_BYTES);

    prep_kernel<<<(18432 + 255) / 256, 256>>>(Kg);

    dim3 grid(64, 16, 4);
    conv_kernel<<<grid, 256, SMEM_BYTES>>>(wu, wl, out, bias);

    bias_reduce<<<5, 64>>>(bu, bl, out);
}